// round 4
// baseline (speedup 1.0000x reference)
#include <cuda_runtime.h>
#include <cuda_bf16.h>
#include <math.h>
#include <stdint.h>

#define BATCH 4
#define SEQ   4096
#define DIM   256
#define TOPK  32
#define ROWS  (BATCH*SEQ)

#define TQ   128
#define TK   64
#define BK   8
#define QSTR 264            // padded row stride (bf16 elems): 528B rows -> conflict-free ldmatrix
#define SCSTR 33            // score buffer stride (floats)

// ---------------- device scratch (allocation-free contract) ----------------
__device__ __nv_bfloat16 g_qhi[ROWS*DIM];
__device__ __nv_bfloat16 g_qlo[ROWS*DIM];
__device__ __nv_bfloat16 g_khi[ROWS*DIM];
__device__ __nv_bfloat16 g_klo[ROWS*DIM];
__device__ float         g_v  [ROWS*DIM];

// SMEM layout (bytes)
#define SM_QH 0
#define SM_QL (SM_QH + TQ*QSTR*2)          // 67584
#define SM_KH (SM_QL + TQ*QSTR*2)          // 135168
#define SM_KL (SM_KH + TK*QSTR*2)          // 168960
#define SM_SC (SM_KL + TK*QSTR*2)          // 202752
#define SM_TOTAL (SM_SC + TQ*SCSTR*4)      // 219648

// ---------------- inline PTX ----------------
__device__ __forceinline__ uint32_t smem_u32(const void* p) {
    uint32_t a;
    asm("{ .reg .u64 t; cvta.to.shared.u64 t, %1; cvt.u32.u64 %0, t; }" : "=r"(a) : "l"(p));
    return a;
}
__device__ __forceinline__ void ldsm4(uint32_t* r, uint32_t addr) {
    asm volatile("ldmatrix.sync.aligned.m8n8.x4.shared.b16 {%0,%1,%2,%3}, [%4];"
        : "=r"(r[0]), "=r"(r[1]), "=r"(r[2]), "=r"(r[3]) : "r"(addr));
}
__device__ __forceinline__ void mma16816(float* c, const uint32_t* a, const uint32_t* b) {
    asm volatile("mma.sync.aligned.m16n8k16.row.col.f32.bf16.bf16.f32 "
        "{%0,%1,%2,%3}, {%4,%5,%6,%7}, {%8,%9}, {%0,%1,%2,%3};"
        : "+f"(c[0]), "+f"(c[1]), "+f"(c[2]), "+f"(c[3])
        : "r"(a[0]), "r"(a[1]), "r"(a[2]), "r"(a[3]), "r"(b[0]), "r"(b[1]));
}

// ---------------------------------------------------------------------------
// Kernel 1: QKV projection; q,k emitted as bf16 hi/lo split, v as fp32.
// ---------------------------------------------------------------------------
__global__ __launch_bounds__(256)
void qkv_kernel(const float* __restrict__ x,
                const float* __restrict__ Wq, const float* __restrict__ bq,
                const float* __restrict__ Wk, const float* __restrict__ bk,
                const float* __restrict__ Wv, const float* __restrict__ bv)
{
    __shared__ float As[BK*128];
    __shared__ float Bs[BK*128];

    const int which = blockIdx.z;
    const float* W    = (which==0) ? Wq : (which==1) ? Wk : Wv;
    const float* bias = (which==0) ? bq : (which==1) ? bk : bv;

    const int tid = threadIdx.x;
    const int tx = tid & 15, ty = tid >> 4;
    const int row0 = blockIdx.x * 128;
    const int col0 = blockIdx.y * 128;

    float acc[8][8];
    #pragma unroll
    for (int i = 0; i < 8; i++)
        #pragma unroll
        for (int j = 0; j < 8; j++) acc[i][j] = 0.f;

    const int amm = tid >> 1;
    const int akk = (tid & 1) * 4;
    const int bkk = tid >> 5;
    const int bnn = (tid & 31) * 4;

    for (int k0 = 0; k0 < DIM; k0 += BK) {
        float4 av = *(const float4*)&x[(row0 + amm)*DIM + k0 + akk];
        As[(akk+0)*128 + amm] = av.x;
        As[(akk+1)*128 + amm] = av.y;
        As[(akk+2)*128 + amm] = av.z;
        As[(akk+3)*128 + amm] = av.w;
        *(float4*)&Bs[bkk*128 + bnn] = *(const float4*)&W[(k0 + bkk)*DIM + col0 + bnn];
        __syncthreads();
        #pragma unroll
        for (int kk = 0; kk < BK; kk++) {
            float a[8], b[8];
            *(float4*)&a[0] = *(const float4*)&As[kk*128 + ty*8];
            *(float4*)&a[4] = *(const float4*)&As[kk*128 + ty*8 + 4];
            *(float4*)&b[0] = *(const float4*)&Bs[kk*128 + tx*8];
            *(float4*)&b[4] = *(const float4*)&Bs[kk*128 + tx*8 + 4];
            #pragma unroll
            for (int i = 0; i < 8; i++)
                #pragma unroll
                for (int j = 0; j < 8; j++)
                    acc[i][j] = fmaf(a[i], b[j], acc[i][j]);
        }
        __syncthreads();
    }

    if (which == 2) {
        #pragma unroll
        for (int i = 0; i < 8; i++) {
            const int r = row0 + ty*8 + i;
            #pragma unroll
            for (int j = 0; j < 8; j += 4) {
                const int c = col0 + tx*8 + j;
                float4 o;
                o.x = acc[i][j+0] + bias[c+0];
                o.y = acc[i][j+1] + bias[c+1];
                o.z = acc[i][j+2] + bias[c+2];
                o.w = acc[i][j+3] + bias[c+3];
                *(float4*)&g_v[(size_t)r*DIM + c] = o;
            }
        }
    } else {
        __nv_bfloat16* hip = (which==0) ? g_qhi : g_khi;
        __nv_bfloat16* lop = (which==0) ? g_qlo : g_klo;
        #pragma unroll
        for (int i = 0; i < 8; i++) {
            const int r = row0 + ty*8 + i;
            #pragma unroll
            for (int j = 0; j < 8; j += 2) {
                const int c = col0 + tx*8 + j;
                float v0 = acc[i][j+0] + bias[c+0];
                float v1 = acc[i][j+1] + bias[c+1];
                __nv_bfloat16 h0 = __float2bfloat16(v0);
                __nv_bfloat16 h1 = __float2bfloat16(v1);
                __nv_bfloat16 l0 = __float2bfloat16(v0 - __bfloat162float(h0));
                __nv_bfloat16 l1 = __float2bfloat16(v1 - __bfloat162float(h1));
                *(__nv_bfloat162*)&hip[(size_t)r*DIM + c] = __halves2bfloat162(h0, h1);
                *(__nv_bfloat162*)&lop[(size_t)r*DIM + c] = __halves2bfloat162(l0, l1);
            }
        }
    }
}

// ---------------------------------------------------------------------------
// Kernel 2: HMMA scores (bf16 hi/lo, fp32 accum) + running top-32 + softmax + AV.
// 256 threads (8 warps), CTA per (batch, 128-query tile). grid = 128.
// Warp tile 32q x 32k; warp grid 4(m) x 2(n); K tile = 64 keys.
// ---------------------------------------------------------------------------
__global__ __launch_bounds__(256, 1)
void attn_kernel(float* __restrict__ out)
{
    extern __shared__ char smem[];
    const uint32_t sb = smem_u32(smem);
    const int tid  = threadIdx.x;
    const int lane = tid & 31;
    const int warp = tid >> 5;
    const int mw   = warp & 3;      // m position (rows mw*32)
    const int nw   = warp >> 2;     // n position (cols nw*32)
    const int b  = blockIdx.x >> 5;
    const int qt = blockIdx.x & 31;
    const int q0 = qt * TQ;
    const size_t rowbase = (size_t)b * SEQ;

    float* Ssc = (float*)(smem + SM_SC);

    // ---- load Q tile (hi/lo) into padded smem ----
    {
        const uint4* qh = (const uint4*)g_qhi + (rowbase + q0) * 32;
        const uint4* ql = (const uint4*)g_qlo + (rowbase + q0) * 32;
        #pragma unroll
        for (int it = 0; it < 16; it++) {
            int idx = it*256 + tid;
            int row = idx >> 5, cc = idx & 31;
            *(uint4*)(smem + SM_QH + row*(QSTR*2) + cc*16) = qh[row*32 + cc];
            *(uint4*)(smem + SM_QL + row*(QSTR*2) + cc*16) = ql[row*32 + cc];
        }
    }

    // per-thread (threads 0..127) running top-k in local memory
    float tv[TOPK];
    int   ti[TOPK];
    #pragma unroll
    for (int j = 0; j < TOPK; j++) { tv[j] = -INFINITY; ti[j] = 0; }
    float thr = -INFINITY;

    // ldmatrix lane-address bases (byte offsets added to k-chunk offset)
    // A (16x16): row = (l&7) + ((l>>3)&1)*8 ; col = (l>>4)*8
    const int a_r  = (lane & 7) + ((lane >> 3) & 1) * 8;
    const int a_c  = (lane >> 4) * 8;
    // B (two 8x16 n-tiles): n = (l&7) + ((l>>4)&1)*8 ; col = ((l>>3)&1)*8
    const int b_r  = (lane & 7) + ((lane >> 4) & 1) * 8;
    const int b_c  = ((lane >> 3) & 1) * 8;

    uint32_t aAh[2], aAl[2], aBh[2], aBl[2];
    #pragma unroll
    for (int mt = 0; mt < 2; mt++) {
        int row = mw*32 + mt*16 + a_r;
        aAh[mt] = sb + SM_QH + (row*QSTR + a_c)*2;
        aAl[mt] = sb + SM_QL + (row*QSTR + a_c)*2;
    }
    #pragma unroll
    for (int pr = 0; pr < 2; pr++) {
        int row = nw*32 + pr*16 + b_r;
        aBh[pr] = sb + SM_KH + (row*QSTR + b_c)*2;
        aBl[pr] = sb + SM_KL + (row*QSTR + b_c)*2;
    }

    const uint4* khsrc = (const uint4*)g_khi + rowbase*32;
    const uint4* klsrc = (const uint4*)g_klo + rowbase*32;

    for (int kt = 0; kt < SEQ/TK; kt++) {
        const int kbase = kt * TK;

        // ---- stream K tile (64 keys, hi+lo) into padded smem ----
        #pragma unroll
        for (int it = 0; it < 8; it++) {
            int idx = it*256 + tid;
            int row = idx >> 5, cc = idx & 31;
            *(uint4*)(smem + SM_KH + row*(QSTR*2) + cc*16) = khsrc[(size_t)(kbase+row)*32 + cc];
            *(uint4*)(smem + SM_KL + row*(QSTR*2) + cc*16) = klsrc[(size_t)(kbase+row)*32 + cc];
        }
        __syncthreads();

        // ---- 3-pass bf16 GEMM: hi*hi + hi*lo + lo*hi ----
        float acc[2][4][4];
        #pragma unroll
        for (int mt = 0; mt < 2; mt++)
            #pragma unroll
            for (int nt = 0; nt < 4; nt++)
                #pragma unroll
                for (int e = 0; e < 4; e++) acc[mt][nt][e] = 0.f;

        #pragma unroll 4
        for (int k0 = 0; k0 < DIM; k0 += 16) {
            uint32_t Ah[2][4], Al[2][4], Bh[2][4], Bl[2][4];
            #pragma unroll
            for (int mt = 0; mt < 2; mt++) {
                ldsm4(Ah[mt], aAh[mt] + k0*2);
                ldsm4(Al[mt], aAl[mt] + k0*2);
            }
            #pragma unroll
            for (int pr = 0; pr < 2; pr++) {
                ldsm4(Bh[pr], aBh[pr] + k0*2);
                ldsm4(Bl[pr], aBl[pr] + k0*2);
            }
            #pragma unroll
            for (int mt = 0; mt < 2; mt++)
                #pragma unroll
                for (int nt = 0; nt < 4; nt++) {
                    const int pr = nt >> 1, hf = (nt & 1) * 2;
                    mma16816(acc[mt][nt], Ah[mt], &Bh[pr][hf]);
                    mma16816(acc[mt][nt], Ah[mt], &Bl[pr][hf]);
                    mma16816(acc[mt][nt], Al[mt], &Bh[pr][hf]);
                }
        }

        // ---- stage + scan in two 32-key halves ----
        #pragma unroll
        for (int half = 0; half < 2; half++) {
            if (nw == half) {
                #pragma unroll
                for (int mt = 0; mt < 2; mt++) {
                    int r0 = mw*32 + mt*16 + (lane >> 2);
                    #pragma unroll
                    for (int nt = 0; nt < 4; nt++) {
                        int cw = nt*8 + (lane & 3)*2;
                        Ssc[ r0      *SCSTR + cw    ] = acc[mt][nt][0];
                        Ssc[ r0      *SCSTR + cw + 1] = acc[mt][nt][1];
                        Ssc[(r0 + 8) *SCSTR + cw    ] = acc[mt][nt][2];
                        Ssc[(r0 + 8) *SCSTR + cw + 1] = acc[mt][nt][3];
                    }
                }
            }
            __syncthreads();
            if (tid < TQ) {
                const int koff = kbase + half*32;
                #pragma unroll 8
                for (int j = 0; j < 32; j++) {
                    float s = Ssc[tid*SCSTR + j];
                    if (s > thr) {
                        int p = TOPK - 1;
                        while (p > 0 && tv[p-1] < s) {
                            tv[p] = tv[p-1];
                            ti[p] = ti[p-1];
                            p--;
                        }
                        tv[p] = s;
                        ti[p] = koff + j;
                        thr = tv[TOPK-1];
                    }
                }
            }
            __syncthreads();
        }
    }

    // ---- softmax over 32 kept (sorted desc; tv[0] = max) -> publish to smem ----
    float* pbuf = (float*)(smem + SM_KH);             // K region is dead now
    int*   ibuf = (int*)  (smem + SM_KH + TQ*TOPK*4);
    if (tid < TQ) {
        float m = tv[0];
        float ssum = 0.f;
        #pragma unroll
        for (int j = 0; j < TOPK; j++) {
            float e = expf(tv[j] - m);
            tv[j] = e;
            ssum += e;
        }
        float inv = 1.f / ssum;
        #pragma unroll
        for (int j = 0; j < TOPK; j++) {
            pbuf[tid*TOPK + j] = tv[j] * inv;
            ibuf[tid*TOPK + j] = ti[j];
        }
    }
    __syncthreads();

    // ---- AV gather: 256 threads, thread owns dim column d = tid ----
    const float* vb = g_v + rowbase*DIM;
    float* ob = out + (rowbase + q0)*DIM;
    const int d = tid;
    for (int qq = 0; qq < TQ; qq++) {
        float accv = 0.f;
        #pragma unroll 8
        for (int j = 0; j < TOPK; j++) {
            float p  = pbuf[qq*TOPK + j];   // broadcast LDS
            int  idx = ibuf[qq*TOPK + j];
            accv = fmaf(p, vb[(size_t)idx*DIM + d], accv);
        }
        ob[(size_t)qq*DIM + d] = accv;
    }
}

extern "C" void kernel_launch(void* const* d_in, const int* in_sizes, int n_in,
                              void* d_out, int out_size)
{
    const float* x  = (const float*)d_in[0];
    const float* Wq = (const float*)d_in[1];
    const float* bq = (const float*)d_in[2];
    const float* Wk = (const float*)d_in[3];
    const float* bk = (const float*)d_in[4];
    const float* Wv = (const float*)d_in[5];
    const float* bv = (const float*)d_in[6];
    float* out = (float*)d_out;

    cudaFuncSetAttribute(attn_kernel,
                         cudaFuncAttributeMaxDynamicSharedMemorySize,
                         SM_TOTAL);

    dim3 g1(ROWS/128, DIM/128, 3);
    qkv_kernel<<<g1, 256>>>(x, Wq, bq, Wk, bk, Wv, bv);

    attn_kernel<<<BATCH*(SEQ/TQ), 256, SM_TOTAL>>>(out);
}

// round 5
// speedup vs baseline: 5.4626x; 5.4626x over previous
#include <cuda_runtime.h>
#include <math.h>
#include <stdint.h>

#define BATCH 4
#define SEQ   4096
#define DIM   256
#define TOPK  32
#define ROWS  (BATCH*SEQ)

#define TQ     128
#define TK     128
#define BK     8
#define SSTR   132   // score stage stride (floats), float4-aligned, 4-way conflict max
#define TSTR   33    // top-list stride (floats/ints), conflict-free column access
#define CHUNKS 4
#define CKEYS  (SEQ/CHUNKS)   // 1024 keys per chunk CTA

// ---------------- device scratch (allocation-free contract) ----------------
__device__ float g_q[ROWS*DIM];
__device__ float g_k[ROWS*DIM];
__device__ float g_v[ROWS*DIM];
// partial top-k lists: [bq(128)][chunk(4)][j(32)][q(128)]
__device__ float g_pv[128*CHUNKS*TOPK*128];
__device__ int   g_pi[128*CHUNKS*TOPK*128];

// ---------------------------------------------------------------------------
// Kernel 1: fused QKV projection (fp32, 128x128x8 tiles, 8x8 microtile).
// ---------------------------------------------------------------------------
__global__ __launch_bounds__(256)
void qkv_kernel(const float* __restrict__ x,
                const float* __restrict__ Wq, const float* __restrict__ bq,
                const float* __restrict__ Wk, const float* __restrict__ bk,
                const float* __restrict__ Wv, const float* __restrict__ bv)
{
    __shared__ float As[BK*128];
    __shared__ float Bs[BK*128];

    const int which = blockIdx.z;
    const float* W    = (which==0) ? Wq : (which==1) ? Wk : Wv;
    const float* bias = (which==0) ? bq : (which==1) ? bk : bv;
    float* outp       = (which==0) ? g_q : (which==1) ? g_k : g_v;

    const int tid = threadIdx.x;
    const int tx = tid & 15, ty = tid >> 4;
    const int row0 = blockIdx.x * 128;
    const int col0 = blockIdx.y * 128;

    float acc[8][8];
    #pragma unroll
    for (int i = 0; i < 8; i++)
        #pragma unroll
        for (int j = 0; j < 8; j++) acc[i][j] = 0.f;

    const int amm = tid >> 1;
    const int akk = (tid & 1) * 4;
    const int bkk = tid >> 5;
    const int bnn = (tid & 31) * 4;

    for (int k0 = 0; k0 < DIM; k0 += BK) {
        float4 av = *(const float4*)&x[(row0 + amm)*DIM + k0 + akk];
        As[(akk+0)*128 + amm] = av.x;
        As[(akk+1)*128 + amm] = av.y;
        As[(akk+2)*128 + amm] = av.z;
        As[(akk+3)*128 + amm] = av.w;
        *(float4*)&Bs[bkk*128 + bnn] = *(const float4*)&W[(k0 + bkk)*DIM + col0 + bnn];
        __syncthreads();
        #pragma unroll
        for (int kk = 0; kk < BK; kk++) {
            float a[8], b[8];
            *(float4*)&a[0] = *(const float4*)&As[kk*128 + ty*8];
            *(float4*)&a[4] = *(const float4*)&As[kk*128 + ty*8 + 4];
            *(float4*)&b[0] = *(const float4*)&Bs[kk*128 + tx*8];
            *(float4*)&b[4] = *(const float4*)&Bs[kk*128 + tx*8 + 4];
            #pragma unroll
            for (int i = 0; i < 8; i++)
                #pragma unroll
                for (int j = 0; j < 8; j++)
                    acc[i][j] = fmaf(a[i], b[j], acc[i][j]);
        }
        __syncthreads();
    }

    #pragma unroll
    for (int i = 0; i < 8; i++) {
        const int r = row0 + ty*8 + i;
        #pragma unroll
        for (int j = 0; j < 8; j += 4) {
            const int c = col0 + tx*8 + j;
            float4 o;
            o.x = acc[i][j+0] + bias[c+0];
            o.y = acc[i][j+1] + bias[c+1];
            o.z = acc[i][j+2] + bias[c+2];
            o.w = acc[i][j+3] + bias[c+3];
            *(float4*)&outp[(size_t)r*DIM + c] = o;
        }
    }
}

// ---------------------------------------------------------------------------
// top-32 insertion into a sorted-descending smem row
// ---------------------------------------------------------------------------
__device__ __forceinline__ void insert_top(float* tv, int* ti, float s, int idx, float& thr)
{
    if (s > thr) {
        int p = TOPK - 1;
        while (p > 0 && tv[p-1] < s) {
            tv[p] = tv[p-1];
            ti[p] = ti[p-1];
            p--;
        }
        tv[p] = s;
        ti[p] = idx;
        thr = tv[TOPK-1];
    }
}

// ---------------------------------------------------------------------------
// Kernel 2: scores (fp32 SIMT GEMM) + per-chunk running top-32.
// grid = (128 bq-tiles, 4 key-chunks), 256 threads, 2 CTAs/SM.
// ---------------------------------------------------------------------------
__global__ __launch_bounds__(256, 2)
void score_kernel()
{
    extern __shared__ float sm[];
    float* As   = sm;                    // [BK][128]
    float* Bs   = As  + BK*128;          // [BK][128]
    float* Ssc  = Bs  + BK*128;          // [128][SSTR]
    float* topV = Ssc + 128*SSTR;        // [128][TSTR]
    int*   topI = (int*)(topV + 128*TSTR);

    const int tid = threadIdx.x;
    const int tx = tid & 15, ty = tid >> 4;
    const int bq = blockIdx.x;
    const int chunk = blockIdx.y;
    const int b  = bq >> 5;
    const int qt = bq & 31;
    const int q0 = qt * TQ;
    const float* qb = g_q + (size_t)b*SEQ*DIM;
    const float* kb = g_k + (size_t)b*SEQ*DIM;

    for (int i = tid; i < 128*TSTR; i += 256) topV[i] = -INFINITY;
    __syncthreads();

    float thr = -INFINITY;
    const int amm = tid >> 1;
    const int akk = (tid & 1) * 4;

    for (int kt = 0; kt < CKEYS/TK; kt++) {
        const int kbase = chunk*CKEYS + kt * TK;

        float acc[8][8];
        #pragma unroll
        for (int i = 0; i < 8; i++)
            #pragma unroll
            for (int j = 0; j < 8; j++) acc[i][j] = 0.f;

        for (int k0 = 0; k0 < DIM; k0 += BK) {
            float4 av = *(const float4*)&qb[(size_t)(q0 + amm)*DIM + k0 + akk];
            As[(akk+0)*128 + amm] = av.x;
            As[(akk+1)*128 + amm] = av.y;
            As[(akk+2)*128 + amm] = av.z;
            As[(akk+3)*128 + amm] = av.w;
            float4 kv = *(const float4*)&kb[(size_t)(kbase + amm)*DIM + k0 + akk];
            Bs[(akk+0)*128 + amm] = kv.x;
            Bs[(akk+1)*128 + amm] = kv.y;
            Bs[(akk+2)*128 + amm] = kv.z;
            Bs[(akk+3)*128 + amm] = kv.w;
            __syncthreads();
            #pragma unroll
            for (int kk = 0; kk < BK; kk++) {
                float a[8], bb[8];
                *(float4*)&a[0]  = *(const float4*)&As[kk*128 + ty*8];
                *(float4*)&a[4]  = *(const float4*)&As[kk*128 + ty*8 + 4];
                *(float4*)&bb[0] = *(const float4*)&Bs[kk*128 + tx*8];
                *(float4*)&bb[4] = *(const float4*)&Bs[kk*128 + tx*8 + 4];
                #pragma unroll
                for (int i = 0; i < 8; i++)
                    #pragma unroll
                    for (int j = 0; j < 8; j++)
                        acc[i][j] = fmaf(a[i], bb[j], acc[i][j]);
            }
            __syncthreads();
        }

        // stage scores
        #pragma unroll
        for (int i = 0; i < 8; i++)
            #pragma unroll
            for (int j = 0; j < 8; j += 4)
                *(float4*)&Ssc[(ty*8 + i)*SSTR + tx*8 + j] = *(float4*)&acc[i][j];
        __syncthreads();

        // running top-32 (threads 0..127, float4 scan)
        if (tid < TQ) {
            float* tv = topV + tid*TSTR;
            int*   ti = topI + tid*TSTR;
            for (int j = 0; j < TK; j += 4) {
                float4 s4 = *(const float4*)&Ssc[tid*SSTR + j];
                insert_top(tv, ti, s4.x, kbase + j + 0, thr);
                insert_top(tv, ti, s4.y, kbase + j + 1, thr);
                insert_top(tv, ti, s4.z, kbase + j + 2, thr);
                insert_top(tv, ti, s4.w, kbase + j + 3, thr);
            }
        }
        __syncthreads();
    }

    // write partial sorted lists, [bq][chunk][j][q] (coalesced per j)
    if (tid < TQ) {
        const size_t base = ((size_t)bq*CHUNKS + chunk)*TOPK*128;
        float* tv = topV + tid*TSTR;
        int*   ti = topI + tid*TSTR;
        #pragma unroll
        for (int j = 0; j < TOPK; j++) {
            g_pv[base + j*128 + tid] = tv[j];
            g_pi[base + j*128 + tid] = ti[j];
        }
    }
}

// ---------------------------------------------------------------------------
// Kernel 3: merge 4 sorted top-32 lists -> softmax -> AV gather.
// grid = 128 (b, q-tile), 256 threads.
// ---------------------------------------------------------------------------
__global__ __launch_bounds__(256, 1)
void merge_kernel(float* __restrict__ out)
{
    extern __shared__ float sm[];
    float* mv   = sm;                         // [4][32][128]
    int*   mi   = (int*)(mv + CHUNKS*TOPK*128);
    float* pbuf = (float*)(mi + CHUNKS*TOPK*128);  // [128][TSTR]
    int*   ibuf = (int*)(pbuf + 128*TSTR);

    const int tid = threadIdx.x;
    const int bq = blockIdx.x;
    const int b  = bq >> 5;
    const int qt = bq & 31;
    const int q0 = qt * TQ;

    const size_t base = (size_t)bq*CHUNKS*TOPK*128;
    for (int i = tid; i < CHUNKS*TOPK*128; i += 256) {
        mv[i] = g_pv[base + i];
        mi[i] = g_pi[base + i];
    }
    __syncthreads();

    if (tid < TQ) {
        int p[CHUNKS] = {0,0,0,0};
        float m = 0.f, ssum = 0.f;
        for (int j = 0; j < TOPK; j++) {
            float best = -INFINITY;
            int bc = 0;
            #pragma unroll
            for (int c = 0; c < CHUNKS; c++) {
                float v = (p[c] < TOPK) ? mv[(c*TOPK + p[c])*128 + tid] : -INFINITY;
                if (v > best) { best = v; bc = c; }
            }
            int idx = mi[(bc*TOPK + p[bc])*128 + tid];
            p[bc]++;
            if (j == 0) m = best;
            float e = expf(best - m);
            pbuf[tid*TSTR + j] = e;
            ibuf[tid*TSTR + j] = idx;
            ssum += e;
        }
        float inv = 1.f / ssum;
        #pragma unroll
        for (int j = 0; j < TOPK; j++) pbuf[tid*TSTR + j] *= inv;
    }
    __syncthreads();

    // AV gather: thread owns dim column d = tid
    const float* vb = g_v + (size_t)b*SEQ*DIM;
    float* ob = out + ((size_t)b*SEQ + q0)*DIM;
    const int d = tid;
    for (int qq = 0; qq < TQ; qq++) {
        float accv = 0.f;
        #pragma unroll 8
        for (int j = 0; j < TOPK; j++) {
            float pp = pbuf[qq*TSTR + j];   // broadcast LDS
            int  idx = ibuf[qq*TSTR + j];
            accv = fmaf(pp, vb[(size_t)idx*DIM + d], accv);
        }
        ob[(size_t)qq*DIM + d] = accv;
    }
}

static const int SCORE_SMEM =
    (BK*128*2 + 128*SSTR + 128*TSTR) * (int)sizeof(float) + 128*TSTR*(int)sizeof(int); // 109,568 B
static const int MERGE_SMEM =
    (CHUNKS*TOPK*128*2 + 128*TSTR*2) * (int)sizeof(float);                             // 164,864 B

extern "C" void kernel_launch(void* const* d_in, const int* in_sizes, int n_in,
                              void* d_out, int out_size)
{
    const float* x  = (const float*)d_in[0];
    const float* Wq = (const float*)d_in[1];
    const float* bq = (const float*)d_in[2];
    const float* Wk = (const float*)d_in[3];
    const float* bk = (const float*)d_in[4];
    const float* Wv = (const float*)d_in[5];
    const float* bv = (const float*)d_in[6];
    float* out = (float*)d_out;

    cudaFuncSetAttribute(score_kernel,
                         cudaFuncAttributeMaxDynamicSharedMemorySize, SCORE_SMEM);
    cudaFuncSetAttribute(merge_kernel,
                         cudaFuncAttributeMaxDynamicSharedMemorySize, MERGE_SMEM);

    dim3 g1(ROWS/128, DIM/128, 3);
    qkv_kernel<<<g1, 256>>>(x, Wq, bq, Wk, bk, Wv, bv);

    dim3 g2(128, CHUNKS);
    score_kernel<<<g2, 256, SCORE_SMEM>>>();

    merge_kernel<<<128, 256, MERGE_SMEM>>>(out);
}